// round 14
// baseline (speedup 1.0000x reference)
#include <cuda_runtime.h>
#include <cstdint>

// PatchPermAugmentation: x (B,T,N,C)=(32,1024,512,3) fp32, perm (B, NB=512) int32.
// out[b,t,n,0] = x[b, perm[b,t/2]*2 + t%2, n, 0]; out[b,t,n,1:] = x[b,t,n,1:].
//
// R12 experiment re-run (infra failed twice; identical source): per-thread
// ILP axis. One CTA per patch block (b, blk) = 768 contiguous float4, with
// 128 threads x 6 front-batched float4 each (MLP_p1=6 vs 3 in all prior
// variants). Everything else identical to the 61.95us best: default cache
// policies, fire-and-exit.
//
// Identity blocks (majority, selection rate 0.25) are a pure vectorized
// copy. Permuted blocks also read the contiguous source block and select
// components by (float4 index) % 3:
//   m==0 -> {x,w} from src; m==1 -> {z}; m==2 -> {y}.
//
// Ledger: best 61.95us (block-CTA, 256t x 3vec4); row-CTA 128t x 3vec4 tied;
// __stcs/-1.0, persistent/-7.0, regcap/-4.1, __ldcs/-0.7 all rejected.
// Run-to-run noise: +/-1us on identical source.

#define BB 32
#define TT 1024
#define NN 512
#define PSZ 2
#define NBLK (TT / PSZ)                 // 512
#define ROW_VEC4 ((NN * 3) / 4)         // 384
#define BLK_VEC4 (PSZ * ROW_VEC4)       // 768

__global__ __launch_bounds__(128)
void patch_perm_kernel(const float4* __restrict__ x,
                       const int* __restrict__ perm,
                       float4* __restrict__ out) {
    const int gblk = blockIdx.x;               // b*NBLK + blk, 0..16383
    const int blk = gblk & (NBLK - 1);
    const int src_blk = perm[gblk];            // perm is (B, NBLK) contiguous

    const size_t base = (size_t)gblk * BLK_VEC4;
    const float4* __restrict__ idr = x + base;
    float4* __restrict__ outr = out + base;

    const int tid = threadIdx.x;               // 0..127
    int idx[6];
    float4 v[6];
#pragma unroll
    for (int k = 0; k < 6; k++) idx[k] = tid + 128 * k;

    // Front-batched identity loads (MLP_p1 = 6)
#pragma unroll
    for (int k = 0; k < 6; k++) v[k] = idr[idx[k]];

    if (src_blk != blk) {                      // uniform branch per CTA
        const float4* __restrict__ sr =
            x + ((size_t)(gblk - blk) + src_blk) * BLK_VEC4;
        float4 s[6];
#pragma unroll
        for (int k = 0; k < 6; k++) s[k] = sr[idx[k]];

#pragma unroll
        for (int k = 0; k < 6; k++) {
            int m = idx[k] % 3;
            if (m == 0)      { v[k].x = s[k].x; v[k].w = s[k].w; }
            else if (m == 1) { v[k].z = s[k].z; }
            else             { v[k].y = s[k].y; }
        }
    }

#pragma unroll
    for (int k = 0; k < 6; k++) outr[idx[k]] = v[k];
}

extern "C" void kernel_launch(void* const* d_in, const int* in_sizes, int n_in,
                              void* d_out, int out_size) {
    const float4* x = (const float4*)d_in[0];
    const int* perm = (const int*)d_in[1];
    float4* out = (float4*)d_out;

    dim3 grid(BB * NBLK);   // 16384 patch blocks
    dim3 block(128);
    patch_perm_kernel<<<grid, block>>>(x, perm, out);
}

// round 15
// speedup vs baseline: 1.0248x; 1.0248x over previous
#include <cuda_runtime.h>
#include <cstdint>

// PatchPermAugmentation: x (B,T,N,C)=(32,1024,512,3) fp32, perm (B, NB=512) int32.
// out[b,t,n,0] = x[b, perm[b,t/2]*2 + t%2, n, 0]; out[b,t,n,1:] = x[b,t,n,1:].
//
// FINAL kernel (best measured: 61.95us dur / 55.68us kernel, 6.26 TB/s =
// 78.2% of HBM spec). Proven DRAM-controller-bound: six structural variants
// (row/block CTAs, ILP 3/6, occ 37-82%) all land in the same 55.6-56.8us
// band; R14's ILP=6 run held 56.0us at occ=37%, proving the SM side has
// latency-hiding surplus in every configuration.
//
// One CTA per patch block (b, blk): rows t=2*blk and 2*blk+1 share one perm
// entry and form 768 contiguous float4 (3 KB). 256 threads x 3 front-batched
// float4, fire-and-exit, default cache policies everywhere.
// Identity blocks (majority, selection rate 0.25) are a pure vectorized
// copy. Permuted blocks also read the contiguous source block (L2-resident
// within the 6 MB batch slab) and select components by (float4 index) % 3:
//   m==0 -> {x,w} from src; m==1 -> {z}; m==2 -> {y}.
//
// Probed and rejected (single-variable ledger):
//  R2  __stcs stores        -1.0us (loses cross-replay L2 carryover)
//  R3  persistent 2048 CTAs -7.0us (loop-carried scoreboards kill MLP)
//  R5  reg cap / occ 82%    -4.1us (cold-path spills; occ not the limiter)
//  R7  __ldcs src loads     -0.7us (worse regalloc + evicts carryover lines)
//  R11 row-CTA vs block-CTA neutral
//  R14 ILP=6 (128t x 6vec4) neutral (DRAM-bound confirmation)

#define BB 32
#define TT 1024
#define NN 512
#define PSZ 2
#define NBLK (TT / PSZ)                 // 512
#define ROW_VEC4 ((NN * 3) / 4)         // 384
#define BLK_VEC4 (PSZ * ROW_VEC4)       // 768

__global__ __launch_bounds__(256)
void patch_perm_kernel(const float4* __restrict__ x,
                       const int* __restrict__ perm,
                       float4* __restrict__ out) {
    const int gblk = blockIdx.x;               // b*NBLK + blk, 0..16383
    const int blk = gblk & (NBLK - 1);
    const int src_blk = perm[gblk];            // perm is (B, NBLK) contiguous

    const size_t base = (size_t)gblk * BLK_VEC4;
    const float4* __restrict__ idr = x + base;
    float4* __restrict__ outr = out + base;

    const int i0 = threadIdx.x;                // 0..255
    const int i1 = i0 + 256;
    const int i2 = i0 + 512;

    // Front-batched identity loads (MLP >= 3)
    float4 v0 = idr[i0];
    float4 v1 = idr[i1];
    float4 v2 = idr[i2];

    if (src_blk != blk) {                      // uniform branch per CTA
        const float4* __restrict__ sr =
            x + ((size_t)(gblk - blk) + src_blk) * BLK_VEC4;
        float4 s0 = sr[i0];
        float4 s1 = sr[i1];
        float4 s2 = sr[i2];

        int m0 = i0 % 3;
        if (m0 == 0)      { v0.x = s0.x; v0.w = s0.w; }
        else if (m0 == 1) { v0.z = s0.z; }
        else              { v0.y = s0.y; }

        int m1 = i1 % 3;
        if (m1 == 0)      { v1.x = s1.x; v1.w = s1.w; }
        else if (m1 == 1) { v1.z = s1.z; }
        else              { v1.y = s1.y; }

        int m2 = i2 % 3;
        if (m2 == 0)      { v2.x = s2.x; v2.w = s2.w; }
        else if (m2 == 1) { v2.z = s2.z; }
        else              { v2.y = s2.y; }
    }

    outr[i0] = v0;
    outr[i1] = v1;
    outr[i2] = v2;
}

extern "C" void kernel_launch(void* const* d_in, const int* in_sizes, int n_in,
                              void* d_out, int out_size) {
    const float4* x = (const float4*)d_in[0];
    const int* perm = (const int*)d_in[1];
    float4* out = (float4*)d_out;

    dim3 grid(BB * NBLK);   // 16384 patch blocks
    dim3 block(256);
    patch_perm_kernel<<<grid, block>>>(x, perm, out);
}